// round 16
// baseline (speedup 1.0000x reference)
#include <cuda_runtime.h>
#include <cuda_bf16.h>

#define CIN   128
#define HH    4
#define CPH   32
#define NVEC  8
#define ALPHA 0.2f
#define MAXN  50048

#define NBLK  592          // 148 SMs x 4 blocks, guaranteed co-resident
#define NTHR  256
#define NTOT  (NBLK * NTHR)
#define EPT   6            // 6 * 151552 = 909312 >= 800000 edges

// Scratch (device globals; allocation is not allowed)
__device__ __align__(16) float g_u[NVEC * CIN];  // fused projection vectors
__device__ float    g_c[NVEC];                   // fused bias constants
__device__ float4   g_S4[MAXN * 2];              // [n*2]=src heads, [n*2+1]=dst heads
__device__ float    g_sum[HH];                   // per-head softmax denominators
__device__ unsigned g_bar[3];                    // monotonic barrier counters (replay-safe)

__device__ __forceinline__ void grid_barrier(int i) {
    __syncthreads();
    if (threadIdx.x == 0) {
        __threadfence();
        unsigned t = atomicAdd(&g_bar[i], 1u);
        unsigned target = t - (t % NBLK) + NBLK;   // next multiple of NBLK
        while ((int)(*(volatile unsigned*)&g_bar[i] - target) < 0) {
            __nanosleep(40);
        }
    }
    __syncthreads();
}

// value-halving fold: after this, lanes with (lane&d)==0 carry a's running
// reduction, lanes with (lane&d)!=0 carry b's.
__device__ __forceinline__ float foldstep(float a, float b, int d, int lane) {
    float as = a + __shfl_xor_sync(0xffffffffu, a, d);
    float bs = b + __shfl_xor_sync(0xffffffffu, b, d);
    return (lane & d) ? bs : as;
}

__global__ __launch_bounds__(NTHR, 4)
void k_fused(const float* __restrict__ x, const int* __restrict__ ei,
             const float* __restrict__ W, const float* __restrict__ b,
             const float* __restrict__ a, float* __restrict__ out,
             int N, int E) {
    __shared__ float sred[8 * HH];

    const int tid  = threadIdx.x;
    const int bid  = blockIdx.x;
    const int warp = tid >> 5;
    const int lane = tid & 31;
    const int gtid = bid * NTHR + tid;

    // ---- phase A: blocks 0..7 compute one fused vector each; rest prefetch ----
    if (bid < NVEC) {
        const int v = bid, h = v & 3, half = v >> 2;
        if (tid < CIN) {
            float acc = 0.f;
            #pragma unroll
            for (int c = 0; c < CPH; c++)
                acc += __ldg(&a[h * 64 + half * 32 + c]) * W[(h * CPH + c) * CIN + tid];
            g_u[v * CIN + tid] = acc;
        } else if (tid == CIN) {
            float acc = 0.f;
            #pragma unroll
            for (int c = 0; c < CPH; c++)
                acc += a[h * 64 + half * 32 + c] * b[h * CPH + c];
            g_c[v] = acc;
        }
        if (bid == 0 && tid < HH) g_sum[tid] = 0.f;
    } else {
        // warm L2 with the edge-index lines phase C will read
        #pragma unroll
        for (int k = 0; k < EPT; k++) {
            int e = gtid + k * NTOT;
            if (e < E) {
                asm volatile("prefetch.global.L2 [%0];" :: "l"(ei + e));
                asm volatile("prefetch.global.L2 [%0];" :: "l"(ei + E + e));
            }
        }
        // warm L2 with ALL x rows this warp will read in phase B (25.6 MB << L2)
        for (int node = bid * 8 + warp; node < N; node += NBLK * 8)
            asm volatile("prefetch.global.L2 [%0];"
                         :: "l"(x + (size_t)node * CIN + lane * 4));
    }

    grid_barrier(0);   // u, c, zeroed sums visible; x/ei streaming into L2

    // ---- phase B: node scores, one warp per node; u in registers; 16 shuffles ----
    {
        float4 uf[NVEC];
        #pragma unroll
        for (int v = 0; v < NVEC; v++)
            uf[v] = *reinterpret_cast<const float4*>(&g_u[v * CIN + lane * 4]);
        const int sel = lane >> 2;                 // value owned by this 4-lane group
        const float cadd = __ldg(&g_c[sel]);

        for (int node = bid * 8 + warp; node < N; node += NBLK * 8) {
            const float4 xf = __ldcs(reinterpret_cast<const float4*>(x + (size_t)node * CIN) + lane);

            float p[NVEC];
            #pragma unroll
            for (int v = 0; v < NVEC; v++)
                p[v] = xf.x * uf[v].x + xf.y * uf[v].y + xf.z * uf[v].z + xf.w * uf[v].w;

            // fold 8 values -> 1 per 4-lane group: 8+4+2 shuffles
            float q0 = foldstep(p[0], p[4], 16, lane);   // bit4 of v
            float q1 = foldstep(p[1], p[5], 16, lane);
            float q2 = foldstep(p[2], p[6], 16, lane);
            float q3 = foldstep(p[3], p[7], 16, lane);
            float r0 = foldstep(q0, q2, 8, lane);        // bit3 of v
            float r1 = foldstep(q1, q3, 8, lane);
            float s  = foldstep(r0, r1, 4, lane);        // bit2 of v
            // finish reduction within the 4-lane group: 2 shuffles
            s += __shfl_xor_sync(0xffffffffu, s, 2);
            s += __shfl_xor_sync(0xffffffffu, s, 1);
            s += cadd;
            if ((lane & 3) == 0)
                reinterpret_cast<float*>(g_S4)[(size_t)node * NVEC + sel] = s;
        }
    }

    grid_barrier(1);   // all S written

    // ---- phase C: edge exp -> out (unnormalized, L2-resident), accumulate sums ----
    float a0 = 0.f, a1 = 0.f, a2 = 0.f, a3 = 0.f;
    float4* o4 = reinterpret_cast<float4*>(out);
    {
        int se[EPT], de[EPT];
        #pragma unroll
        for (int k = 0; k < EPT; k++) {
            int e = gtid + k * NTOT;
            if (e < E) { se[k] = ei[e]; de[k] = ei[E + e]; }
            else       { se[k] = 0;     de[k] = 0; }
        }
        #pragma unroll
        for (int k = 0; k < EPT; k++) {
            int e = gtid + k * NTOT;
            if (e < E) {
                float4 Ss = __ldcg(&g_S4[(size_t)se[k] * 2]);
                float4 Sd = __ldcg(&g_S4[(size_t)de[k] * 2 + 1]);
                float l0 = Ss.x + Sd.x; l0 = (l0 > 0.f) ? l0 : ALPHA * l0;
                float l1 = Ss.y + Sd.y; l1 = (l1 > 0.f) ? l1 : ALPHA * l1;
                float l2 = Ss.z + Sd.z; l2 = (l2 > 0.f) ? l2 : ALPHA * l2;
                float l3 = Ss.w + Sd.w; l3 = (l3 > 0.f) ? l3 : ALPHA * l3;
                float e0 = __expf(l0), e1 = __expf(l1), e2 = __expf(l2), e3 = __expf(l3);
                o4[e] = make_float4(e0, e1, e2, e3);   // plain store: stays in L2
                a0 += e0; a1 += e1; a2 += e2; a3 += e3;
            }
        }
    }
    #pragma unroll
    for (int off = 16; off > 0; off >>= 1) {
        a0 += __shfl_down_sync(0xffffffffu, a0, off);
        a1 += __shfl_down_sync(0xffffffffu, a1, off);
        a2 += __shfl_down_sync(0xffffffffu, a2, off);
        a3 += __shfl_down_sync(0xffffffffu, a3, off);
    }
    if (lane == 0) {
        sred[warp * HH + 0] = a0;
        sred[warp * HH + 1] = a1;
        sred[warp * HH + 2] = a2;
        sred[warp * HH + 3] = a3;
    }
    __syncthreads();
    if (tid < HH) {
        float s = 0.f;
        #pragma unroll
        for (int w = 0; w < 8; w++) s += sred[w * HH + tid];
        atomicAdd(&g_sum[tid], s);
    }

    grid_barrier(2);   // sums complete

    // ---- phase D: reload own stores from L2, normalize, stream final write ----
    const float inv0 = __frcp_rn(((volatile float*)g_sum)[0]);
    const float inv1 = __frcp_rn(((volatile float*)g_sum)[1]);
    const float inv2 = __frcp_rn(((volatile float*)g_sum)[2]);
    const float inv3 = __frcp_rn(((volatile float*)g_sum)[3]);
    #pragma unroll
    for (int k = 0; k < EPT; k++) {
        int e = gtid + k * NTOT;
        if (e < E) {
            float4 o = o4[e];                      // same-thread reload: L2 hit
            o.x *= inv0; o.y *= inv1; o.z *= inv2; o.w *= inv3;
            __stcs(&o4[e], o);
        }
    }
}

extern "C" void kernel_launch(void* const* d_in, const int* in_sizes, int n_in,
                              void* d_out, int out_size) {
    const float* x  = (const float*)d_in[0];   // node_feats [N,128]
    const int*   ei = (const int*)d_in[1];     // edge_index [2,E] int32
    const float* W  = (const float*)d_in[2];   // [128,128]
    const float* b  = (const float*)d_in[3];   // [128]
    const float* a  = (const float*)d_in[4];   // [4,64]

    int N = in_sizes[0] / CIN;
    int E = in_sizes[1] / 2;
    float* out = (float*)d_out;

    k_fused<<<NBLK, NTHR>>>(x, ei, W, b, a, out, N, E);
}

// round 17
// speedup vs baseline: 1.0018x; 1.0018x over previous
#include <cuda_runtime.h>
#include <cuda_bf16.h>

#define CIN   128
#define HH    4
#define CPH   32
#define NVEC  8
#define ALPHA 0.2f
#define MAXN  50048

#define NBLK  592          // 148 SMs x 4 blocks, guaranteed co-resident
#define NTHR  256
#define NTOT  (NBLK * NTHR)
#define EPT   6            // 6 * 151552 = 909312 >= 800000 edges

// Scratch (device globals; allocation is not allowed)
__device__ __align__(16) float g_u[NVEC * CIN];  // fused projection vectors
__device__ float    g_c[NVEC];                   // fused bias constants
__device__ float4   g_S4[MAXN * 2];              // [n*2]=src heads, [n*2+1]=dst heads
__device__ float    g_sum[HH];                   // per-head softmax denominators
__device__ unsigned g_bar[3];                    // monotonic barrier counters (replay-safe)

__device__ __forceinline__ void grid_barrier(int i) {
    __syncthreads();
    if (threadIdx.x == 0) {
        __threadfence();
        unsigned t = atomicAdd(&g_bar[i], 1u);
        unsigned target = t - (t % NBLK) + NBLK;   // next multiple of NBLK
        while ((int)(*(volatile unsigned*)&g_bar[i] - target) < 0) {
            __nanosleep(40);
        }
    }
    __syncthreads();
}

// FMA-pipe exp: avoids MUFU (rt_SMSP=8 -> 0.5 op/cyc/SM, the kernel's real
// bottleneck). Magic-number range reduction + degree-5 poly for 2^f.
// Valid for |x| < ~80; rel err ~1e-7.
__device__ __forceinline__ float fexp(float x) {
    const float LOG2E = 1.4426950408889634f;
    const float MAGIC = 12582912.0f;               // 1.5 * 2^23
    float t  = fmaf(x, LOG2E, MAGIC);              // mantissa low bits hold rint(y)
    int   ni = __float_as_int(t) - 0x4B400000;     // n as signed int
    float n  = t - MAGIC;                          // n as float (exact)
    float f  = fmaf(x, LOG2E, -n);                 // f = y - n in [-0.5, 0.5]
    float p  =           1.333355814642e-3f;
    p = fmaf(p, f, 9.618129107629e-3f);
    p = fmaf(p, f, 5.5504108664822e-2f);
    p = fmaf(p, f, 2.40226506959101e-1f);
    p = fmaf(p, f, 6.93147180559945e-1f);
    p = fmaf(p, f, 1.0f);                          // p = 2^f
    return __int_as_float(__float_as_int(p) + (ni << 23));  // p * 2^n
}

// value-halving fold: after this, lanes with (lane&d)==0 carry a's running
// reduction, lanes with (lane&d)!=0 carry b's.
__device__ __forceinline__ float foldstep(float a, float b, int d, int lane) {
    float as = a + __shfl_xor_sync(0xffffffffu, a, d);
    float bs = b + __shfl_xor_sync(0xffffffffu, b, d);
    return (lane & d) ? bs : as;
}

__global__ __launch_bounds__(NTHR, 4)
void k_fused(const float* __restrict__ x, const int* __restrict__ ei,
             const float* __restrict__ W, const float* __restrict__ b,
             const float* __restrict__ a, float* __restrict__ out,
             int N, int E) {
    __shared__ float sred[8 * HH];

    const int tid  = threadIdx.x;
    const int bid  = blockIdx.x;
    const int warp = tid >> 5;
    const int lane = tid & 31;
    const int gtid = bid * NTHR + tid;

    // ---- phase A: blocks 0..7 compute one fused vector each; rest prefetch ----
    if (bid < NVEC) {
        const int v = bid, h = v & 3, half = v >> 2;
        if (tid < CIN) {
            float acc = 0.f;
            #pragma unroll
            for (int c = 0; c < CPH; c++)
                acc += __ldg(&a[h * 64 + half * 32 + c]) * W[(h * CPH + c) * CIN + tid];
            g_u[v * CIN + tid] = acc;
        } else if (tid == CIN) {
            float acc = 0.f;
            #pragma unroll
            for (int c = 0; c < CPH; c++)
                acc += a[h * 64 + half * 32 + c] * b[h * CPH + c];
            g_c[v] = acc;
        }
        if (bid == 0 && tid < HH) g_sum[tid] = 0.f;
    } else {
        // warm L2 with the edge-index lines phase C will read
        #pragma unroll
        for (int k = 0; k < EPT; k++) {
            int e = gtid + k * NTOT;
            if (e < E) {
                asm volatile("prefetch.global.L2 [%0];" :: "l"(ei + e));
                asm volatile("prefetch.global.L2 [%0];" :: "l"(ei + E + e));
            }
        }
        // warm L2 with ALL x rows this warp will read in phase B (25.6 MB << L2)
        for (int node = bid * 8 + warp; node < N; node += NBLK * 8)
            asm volatile("prefetch.global.L2 [%0];"
                         :: "l"(x + (size_t)node * CIN + lane * 4));
    }

    grid_barrier(0);   // u, c, zeroed sums visible; x/ei streaming into L2

    // ---- phase B: node scores, one warp per node; u in registers; 16 shuffles ----
    {
        float4 uf[NVEC];
        #pragma unroll
        for (int v = 0; v < NVEC; v++)
            uf[v] = *reinterpret_cast<const float4*>(&g_u[v * CIN + lane * 4]);
        const int sel = lane >> 2;                 // value owned by this 4-lane group
        const float cadd = __ldg(&g_c[sel]);

        for (int node = bid * 8 + warp; node < N; node += NBLK * 8) {
            const float4 xf = __ldcs(reinterpret_cast<const float4*>(x + (size_t)node * CIN) + lane);

            float p[NVEC];
            #pragma unroll
            for (int v = 0; v < NVEC; v++)
                p[v] = xf.x * uf[v].x + xf.y * uf[v].y + xf.z * uf[v].z + xf.w * uf[v].w;

            // fold 8 values -> 1 per 4-lane group: 8+4+2 shuffles
            float q0 = foldstep(p[0], p[4], 16, lane);
            float q1 = foldstep(p[1], p[5], 16, lane);
            float q2 = foldstep(p[2], p[6], 16, lane);
            float q3 = foldstep(p[3], p[7], 16, lane);
            float r0 = foldstep(q0, q2, 8, lane);
            float r1 = foldstep(q1, q3, 8, lane);
            float s  = foldstep(r0, r1, 4, lane);
            s += __shfl_xor_sync(0xffffffffu, s, 2);
            s += __shfl_xor_sync(0xffffffffu, s, 1);
            s += cadd;
            if ((lane & 3) == 0)
                reinterpret_cast<float*>(g_S4)[(size_t)node * NVEC + sel] = s;
        }
    }

    grid_barrier(1);   // all S written

    // ---- phase C: edge exp -> out (unnormalized, L2-resident), accumulate sums ----
    float a0 = 0.f, a1 = 0.f, a2 = 0.f, a3 = 0.f;
    float4* o4 = reinterpret_cast<float4*>(out);
    {
        int se[EPT], de[EPT];
        #pragma unroll
        for (int k = 0; k < EPT; k++) {
            int e = gtid + k * NTOT;
            if (e < E) { se[k] = ei[e]; de[k] = ei[E + e]; }
            else       { se[k] = 0;     de[k] = 0; }
        }
        #pragma unroll
        for (int k = 0; k < EPT; k++) {
            int e = gtid + k * NTOT;
            if (e < E) {
                float4 Ss = __ldcg(&g_S4[(size_t)se[k] * 2]);
                float4 Sd = __ldcg(&g_S4[(size_t)de[k] * 2 + 1]);
                float l0 = Ss.x + Sd.x; l0 = (l0 > 0.f) ? l0 : ALPHA * l0;
                float l1 = Ss.y + Sd.y; l1 = (l1 > 0.f) ? l1 : ALPHA * l1;
                float l2 = Ss.z + Sd.z; l2 = (l2 > 0.f) ? l2 : ALPHA * l2;
                float l3 = Ss.w + Sd.w; l3 = (l3 > 0.f) ? l3 : ALPHA * l3;
                float e0 = fexp(l0), e1 = fexp(l1), e2 = fexp(l2), e3 = fexp(l3);
                o4[e] = make_float4(e0, e1, e2, e3);   // plain store: stays in L2
                a0 += e0; a1 += e1; a2 += e2; a3 += e3;
            }
        }
    }
    #pragma unroll
    for (int off = 16; off > 0; off >>= 1) {
        a0 += __shfl_down_sync(0xffffffffu, a0, off);
        a1 += __shfl_down_sync(0xffffffffu, a1, off);
        a2 += __shfl_down_sync(0xffffffffu, a2, off);
        a3 += __shfl_down_sync(0xffffffffu, a3, off);
    }
    if (lane == 0) {
        sred[warp * HH + 0] = a0;
        sred[warp * HH + 1] = a1;
        sred[warp * HH + 2] = a2;
        sred[warp * HH + 3] = a3;
    }
    __syncthreads();
    if (tid < HH) {
        float s = 0.f;
        #pragma unroll
        for (int w = 0; w < 8; w++) s += sred[w * HH + tid];
        atomicAdd(&g_sum[tid], s);
    }

    grid_barrier(2);   // sums complete

    // ---- phase D: reload own stores from L2, normalize, stream final write ----
    const float inv0 = __frcp_rn(((volatile float*)g_sum)[0]);
    const float inv1 = __frcp_rn(((volatile float*)g_sum)[1]);
    const float inv2 = __frcp_rn(((volatile float*)g_sum)[2]);
    const float inv3 = __frcp_rn(((volatile float*)g_sum)[3]);
    #pragma unroll
    for (int k = 0; k < EPT; k++) {
        int e = gtid + k * NTOT;
        if (e < E) {
            float4 o = o4[e];                      // same-thread reload: L2 hit
            o.x *= inv0; o.y *= inv1; o.z *= inv2; o.w *= inv3;
            __stcs(&o4[e], o);
        }
    }
}

extern "C" void kernel_launch(void* const* d_in, const int* in_sizes, int n_in,
                              void* d_out, int out_size) {
    const float* x  = (const float*)d_in[0];   // node_feats [N,128]
    const int*   ei = (const int*)d_in[1];     // edge_index [2,E] int32
    const float* W  = (const float*)d_in[2];   // [128,128]
    const float* b  = (const float*)d_in[3];   // [128]
    const float* a  = (const float*)d_in[4];   // [4,64]

    int N = in_sizes[0] / CIN;
    int E = in_sizes[1] / 2;
    float* out = (float*)d_out;

    k_fused<<<NBLK, NTHR>>>(x, ei, W, b, a, out, N, E);
}